// round 1
// baseline (speedup 1.0000x reference)
#include <cuda_runtime.h>
#include <cstdint>

// ---------------------------------------------------------------------------
// Problem constants (fixed shapes from reference):
//   N = 2048 jobs, M = 2048 machines, D_J = D_M = 16, D_G = 8, HIDDEN = 64
// Q[n,m] = b2 + sum_h w2[h] * relu( hj[n,h] + hm[m,h] + hg[h] )
// ---------------------------------------------------------------------------

#define NMAX 2048
#define HID  64
#define HP   32   // h pairs

// Scratch: transposed, h-pair-packed feature rows.
// g_aT[h2][n] = pack(hj[n][2*h2], hj[n][2*h2+1])
// g_bT[h2][m] = pack(hm'[m][2*h2], hm'[m][2*h2+1])   (hm' = hm + hg, b1 folded)
__device__ unsigned long long g_aT[HP][NMAX];
__device__ unsigned long long g_bT[HP][NMAX];
__device__ unsigned long long g_w2[HP];

__device__ __forceinline__ unsigned long long pack2(float lo, float hi) {
    return (unsigned long long)__float_as_uint(lo) |
           ((unsigned long long)__float_as_uint(hi) << 32);
}

// ---------------------------------------------------------------------------
// Precompute kernel: one thread per job row / machine row (+32 for w2 pack).
// ---------------------------------------------------------------------------
__global__ void precompute_kernel(
    const float* __restrict__ job, const float* __restrict__ mac,
    const float* __restrict__ gvec,
    const float* __restrict__ Wj, const float* __restrict__ bj,
    const float* __restrict__ Wm, const float* __restrict__ bm,
    const float* __restrict__ Wg, const float* __restrict__ bg,
    const float* __restrict__ W1, const float* __restrict__ b1,
    const float* __restrict__ W2,
    int n, int m)
{
    int t = blockIdx.x * blockDim.x + threadIdx.x;
    if (t < n) {
        // job row: hj[h] = sum_j relu(x*Wj[j]+bj[j]) * W1[j][h]
        float x = job[t];
        float h[HID];
        #pragma unroll
        for (int hh = 0; hh < HID; ++hh) h[hh] = 0.0f;
        for (int j = 0; j < 16; ++j) {
            float f = fmaxf(fmaf(x, Wj[j], bj[j]), 0.0f);
            #pragma unroll
            for (int hh = 0; hh < HID; ++hh)
                h[hh] = fmaf(f, W1[j * HID + hh], h[hh]);
        }
        #pragma unroll
        for (int h2 = 0; h2 < HP; ++h2)
            g_aT[h2][t] = pack2(h[2 * h2], h[2 * h2 + 1]);
    } else if (t < n + m) {
        // machine row: hm'[h] = b1[h] + hg[h]-part + hm[h]
        int mm = t - n;
        float x = mac[mm];
        float h[HID];
        #pragma unroll
        for (int hh = 0; hh < HID; ++hh) h[hh] = b1[hh];
        // global path (redundant per thread; tiny)
        for (int k = 0; k < 8; ++k) {
            float gf = bg[k];
            #pragma unroll
            for (int i = 0; i < 8; ++i)
                gf = fmaf(gvec[i], Wg[i * 8 + k], gf);
            gf = fmaxf(gf, 0.0f);
            #pragma unroll
            for (int hh = 0; hh < HID; ++hh)
                h[hh] = fmaf(gf, W1[(32 + k) * HID + hh], h[hh]);
        }
        for (int j = 0; j < 16; ++j) {
            float f = fmaxf(fmaf(x, Wm[j], bm[j]), 0.0f);
            #pragma unroll
            for (int hh = 0; hh < HID; ++hh)
                h[hh] = fmaf(f, W1[(16 + j) * HID + hh], h[hh]);
        }
        #pragma unroll
        for (int h2 = 0; h2 < HP; ++h2)
            g_bT[h2][mm] = pack2(h[2 * h2], h[2 * h2 + 1]);
    } else if (t < n + m + HP) {
        int h2 = t - (n + m);
        g_w2[h2] = pack2(W2[2 * h2], W2[2 * h2 + 1]);
    }
}

// ---------------------------------------------------------------------------
// Core op: acc(f32x2) += relu2(a + b) * w, packed add/fma on the fma pipe,
// scalar FMNMX relu on the alu pipe. mov.b64 pack/unpack expected to be
// eliminated by ptxas register-pair allocation.
// ---------------------------------------------------------------------------
__device__ __forceinline__ void step(unsigned long long& acc,
                                     unsigned long long a,
                                     unsigned long long b,
                                     unsigned long long w)
{
    asm("{\n\t"
        ".reg .b64 t;\n\t"
        ".reg .f32 lo, hi;\n\t"
        "add.rn.f32x2 t, %1, %2;\n\t"
        "mov.b64 {lo, hi}, t;\n\t"
        "max.f32 lo, lo, 0f00000000;\n\t"
        "max.f32 hi, hi, 0f00000000;\n\t"
        "mov.b64 t, {lo, hi};\n\t"
        "fma.rn.f32x2 %0, t, %3, %0;\n\t"
        "}"
        : "+l"(acc)
        : "l"(a), "l"(b), "l"(w));
}

// ---------------------------------------------------------------------------
// Main kernel: block tile 128(n) x 64(m), 256 threads, 8x4 per thread.
// ---------------------------------------------------------------------------
__global__ void __launch_bounds__(256, 2) qmain_kernel(
    const float* __restrict__ b2, float* __restrict__ out, int N, int M)
{
    __shared__ unsigned long long sA[HP][128];  // 32 KB
    __shared__ unsigned long long sB[HP][64];   // 16 KB  (total = 48 KB exactly)

    const int tid = threadIdx.x;
    const int nBase = blockIdx.y * 128;
    const int mBase = blockIdx.x * 64;

    // Fill sA: 4096 entries / 256 threads = 16 each, coalesced.
    #pragma unroll
    for (int i = 0; i < 16; ++i) {
        int idx = tid + i * 256;
        int h2 = idx >> 7, nl = idx & 127;
        sA[h2][nl] = g_aT[h2][nBase + nl];
    }
    // Fill sB: 2048 entries / 256 threads = 8 each.
    #pragma unroll
    for (int i = 0; i < 8; ++i) {
        int idx = tid + i * 256;
        int h2 = idx >> 6, ml = idx & 63;
        sB[h2][ml] = g_bT[h2][mBase + ml];
    }
    __syncthreads();

    const int tx = tid & 15;        // m dimension
    const int ty = tid >> 4;        // n dimension
    const int n0 = ty * 8;
    const int m0 = tx * 4;

    unsigned long long acc[8][4];
    #pragma unroll
    for (int i = 0; i < 8; ++i)
        #pragma unroll
        for (int j = 0; j < 4; ++j)
            acc[i][j] = 0ull;

    #pragma unroll 2
    for (int h2 = 0; h2 < HP; ++h2) {
        unsigned long long w = g_w2[h2];
        ulonglong2 a0 = *(const ulonglong2*)&sA[h2][n0 + 0];
        ulonglong2 a1 = *(const ulonglong2*)&sA[h2][n0 + 2];
        ulonglong2 a2 = *(const ulonglong2*)&sA[h2][n0 + 4];
        ulonglong2 a3 = *(const ulonglong2*)&sA[h2][n0 + 6];
        ulonglong2 b0 = *(const ulonglong2*)&sB[h2][m0 + 0];
        ulonglong2 b1 = *(const ulonglong2*)&sB[h2][m0 + 2];
        unsigned long long A[8] = {a0.x, a0.y, a1.x, a1.y, a2.x, a2.y, a3.x, a3.y};
        unsigned long long B[4] = {b0.x, b0.y, b1.x, b1.y};
        #pragma unroll
        for (int i = 0; i < 8; ++i)
            #pragma unroll
            for (int j = 0; j < 4; ++j)
                step(acc[i][j], A[i], B[j], w);
    }

    // Epilogue: combine h-pair lanes, add b2, vectorized store.
    const float bconst = b2[0];
    #pragma unroll
    for (int i = 0; i < 8; ++i) {
        float r[4];
        #pragma unroll
        for (int j = 0; j < 4; ++j) {
            unsigned long long u = acc[i][j];
            r[j] = __uint_as_float((unsigned)u) +
                   __uint_as_float((unsigned)(u >> 32)) + bconst;
        }
        float4 v = make_float4(r[0], r[1], r[2], r[3]);
        *(float4*)&out[(size_t)(nBase + n0 + i) * M + (mBase + m0)] = v;
    }
}

// ---------------------------------------------------------------------------
// Launch
// ---------------------------------------------------------------------------
extern "C" void kernel_launch(void* const* d_in, const int* in_sizes, int n_in,
                              void* d_out, int out_size)
{
    const float* job  = (const float*)d_in[0];
    const float* mac  = (const float*)d_in[1];
    const float* gvec = (const float*)d_in[2];
    const float* Wj   = (const float*)d_in[3];
    const float* bj   = (const float*)d_in[4];
    const float* Wm   = (const float*)d_in[5];
    const float* bm   = (const float*)d_in[6];
    const float* Wg   = (const float*)d_in[7];
    const float* bg   = (const float*)d_in[8];
    const float* W1   = (const float*)d_in[9];
    const float* b1   = (const float*)d_in[10];
    const float* W2   = (const float*)d_in[11];
    const float* b2   = (const float*)d_in[12];
    float* out = (float*)d_out;

    const int N = in_sizes[0];
    const int M = in_sizes[1];

    int pre_threads = N + M + HP;
    precompute_kernel<<<(pre_threads + 255) / 256, 256>>>(
        job, mac, gvec, Wj, bj, Wm, bm, Wg, bg, W1, b1, W2, N, M);

    dim3 grid(M / 64, N / 128);
    qmain_kernel<<<grid, 256>>>(b2, out, N, M);
}

// round 2
// speedup vs baseline: 1.4387x; 1.4387x over previous
#include <cuda_runtime.h>
#include <cstdint>

// ---------------------------------------------------------------------------
// Q[n,m] = b2 + sum_h w2[h] * relu( hj[n,h] + hm'[m,h] )
//   hm' = hm + hg + b1 folded into machine rows.
// N = M = 2048, HIDDEN = 64. Feature rows precomputed, h-pair packed (f32x2).
// ---------------------------------------------------------------------------

#define NMAX 2048
#define HID  64
#define HP   32   // h pairs

// g_aT[h2][n] = pack(hj[n][2h2], hj[n][2h2+1])
// g_bT[h2][m] = pack(hm'[m][2h2], hm'[m][2h2+1])
__device__ unsigned long long g_aT[HP][NMAX];
__device__ unsigned long long g_bT[HP][NMAX];

__device__ __forceinline__ unsigned long long pack2(float lo, float hi) {
    return (unsigned long long)__float_as_uint(lo) |
           ((unsigned long long)__float_as_uint(hi) << 32);
}

// ---------------------------------------------------------------------------
// Precompute: one warp per row. lane = h-pair index (0..31).
// Each lane computes h[2*lane], h[2*lane+1]. W1 loads are coalesced float2.
// Rows 0..N-1 : job rows.  Rows N..N+M-1 : machine rows.
// ---------------------------------------------------------------------------
__global__ void __launch_bounds__(256) precompute_kernel(
    const float* __restrict__ job, const float* __restrict__ mac,
    const float* __restrict__ gvec,
    const float* __restrict__ Wj, const float* __restrict__ bj,
    const float* __restrict__ Wm, const float* __restrict__ bm,
    const float* __restrict__ Wg, const float* __restrict__ bg,
    const float* __restrict__ W1, const float* __restrict__ b1,
    int n, int m)
{
    const int row  = blockIdx.x * 8 + (threadIdx.x >> 5);
    const int lane = threadIdx.x & 31;

    if (row < n) {
        // job row: h = sum_j relu(x*Wj[j]+bj[j]) * W1[j][:]
        const float x = job[row];
        float h0 = 0.0f, h1 = 0.0f;
        #pragma unroll
        for (int j = 0; j < 16; ++j) {
            float f = fmaxf(fmaf(x, Wj[j], bj[j]), 0.0f);
            float2 w = *(const float2*)&W1[j * HID + 2 * lane];
            h0 = fmaf(f, w.x, h0);
            h1 = fmaf(f, w.y, h1);
        }
        g_aT[lane][row] = pack2(h0, h1);
    } else if (row < n + m) {
        const int mm = row - n;
        const float x = mac[mm];
        float2 bb = *(const float2*)&b1[2 * lane];
        float h0 = bb.x, h1 = bb.y;
        // global path (redundant per lane; tiny)
        #pragma unroll
        for (int k = 0; k < 8; ++k) {
            float gf = bg[k];
            #pragma unroll
            for (int i = 0; i < 8; ++i)
                gf = fmaf(gvec[i], Wg[i * 8 + k], gf);
            gf = fmaxf(gf, 0.0f);
            float2 w = *(const float2*)&W1[(32 + k) * HID + 2 * lane];
            h0 = fmaf(gf, w.x, h0);
            h1 = fmaf(gf, w.y, h1);
        }
        #pragma unroll
        for (int j = 0; j < 16; ++j) {
            float f = fmaxf(fmaf(x, Wm[j], bm[j]), 0.0f);
            float2 w = *(const float2*)&W1[(16 + j) * HID + 2 * lane];
            h0 = fmaf(f, w.x, h0);
            h1 = fmaf(f, w.y, h1);
        }
        g_bT[lane][mm] = pack2(h0, h1);
    }
}

// ---------------------------------------------------------------------------
// Core step: acc(f32x2) += relu2(a + b) * w.
// add/fma packed (fma pipe), scalar FMNMX relu (alu pipe). The mov.b64
// pack/unpack is eliminated by ptxas register-pair allocation.
// ---------------------------------------------------------------------------
__device__ __forceinline__ void step(unsigned long long& acc,
                                     unsigned long long a,
                                     unsigned long long b,
                                     unsigned long long w)
{
    asm("{\n\t"
        ".reg .b64 t;\n\t"
        ".reg .f32 lo, hi;\n\t"
        "add.rn.f32x2 t, %1, %2;\n\t"
        "mov.b64 {lo, hi}, t;\n\t"
        "max.f32 lo, lo, 0f00000000;\n\t"
        "max.f32 hi, hi, 0f00000000;\n\t"
        "mov.b64 t, {lo, hi};\n\t"
        "fma.rn.f32x2 %0, t, %3, %0;\n\t"
        "}"
        : "+l"(acc)
        : "l"(a), "l"(b), "l"(w));
}

// ---------------------------------------------------------------------------
// Main kernel: block tile 128(n) x 64(m), 256 threads, 8x4 per thread.
// w2 staged in shared memory (no in-loop LDG).
// ---------------------------------------------------------------------------
__global__ void __launch_bounds__(256, 2) qmain_kernel(
    const float* __restrict__ W2, const float* __restrict__ b2,
    float* __restrict__ out, int N, int M)
{
    __shared__ unsigned long long sA[HP][128];  // 32 KB
    __shared__ unsigned long long sB[HP][64];   // 16 KB
    __shared__ unsigned long long sW[HP];       // 256 B

    const int tid = threadIdx.x;
    const int nBase = blockIdx.y * 128;
    const int mBase = blockIdx.x * 64;

    // Stage w2 pairs.
    if (tid < HP) {
        float2 w = *(const float2*)&W2[2 * tid];
        sW[tid] = pack2(w.x, w.y);
    }
    // Fill sA: 4096 entries / 256 threads = 16 each, coalesced.
    #pragma unroll
    for (int i = 0; i < 16; ++i) {
        int idx = tid + i * 256;
        int h2 = idx >> 7, nl = idx & 127;
        sA[h2][nl] = g_aT[h2][nBase + nl];
    }
    // Fill sB: 2048 entries / 256 threads = 8 each.
    #pragma unroll
    for (int i = 0; i < 8; ++i) {
        int idx = tid + i * 256;
        int h2 = idx >> 6, ml = idx & 63;
        sB[h2][ml] = g_bT[h2][mBase + ml];
    }
    __syncthreads();

    const int tx = tid & 15;        // m dimension
    const int ty = tid >> 4;        // n dimension
    const int n0 = ty * 8;
    const int m0 = tx * 4;

    unsigned long long acc[8][4];
    #pragma unroll
    for (int i = 0; i < 8; ++i)
        #pragma unroll
        for (int j = 0; j < 4; ++j)
            acc[i][j] = 0ull;

    #pragma unroll 2
    for (int h2 = 0; h2 < HP; ++h2) {
        unsigned long long w = sW[h2];
        ulonglong2 a0 = *(const ulonglong2*)&sA[h2][n0 + 0];
        ulonglong2 a1 = *(const ulonglong2*)&sA[h2][n0 + 2];
        ulonglong2 a2 = *(const ulonglong2*)&sA[h2][n0 + 4];
        ulonglong2 a3 = *(const ulonglong2*)&sA[h2][n0 + 6];
        ulonglong2 b0 = *(const ulonglong2*)&sB[h2][m0 + 0];
        ulonglong2 b1 = *(const ulonglong2*)&sB[h2][m0 + 2];
        unsigned long long A[8] = {a0.x, a0.y, a1.x, a1.y, a2.x, a2.y, a3.x, a3.y};
        unsigned long long B[4] = {b0.x, b0.y, b1.x, b1.y};
        #pragma unroll
        for (int i = 0; i < 8; ++i)
            #pragma unroll
            for (int j = 0; j < 4; ++j)
                step(acc[i][j], A[i], B[j], w);
    }

    // Epilogue: combine h-pair lanes, add b2, vectorized store.
    const float bconst = b2[0];
    #pragma unroll
    for (int i = 0; i < 8; ++i) {
        float r[4];
        #pragma unroll
        for (int j = 0; j < 4; ++j) {
            unsigned long long u = acc[i][j];
            r[j] = __uint_as_float((unsigned)u) +
                   __uint_as_float((unsigned)(u >> 32)) + bconst;
        }
        float4 v = make_float4(r[0], r[1], r[2], r[3]);
        *(float4*)&out[(size_t)(nBase + n0 + i) * M + (mBase + m0)] = v;
    }
}

// ---------------------------------------------------------------------------
// Launch
// ---------------------------------------------------------------------------
extern "C" void kernel_launch(void* const* d_in, const int* in_sizes, int n_in,
                              void* d_out, int out_size)
{
    const float* job  = (const float*)d_in[0];
    const float* mac  = (const float*)d_in[1];
    const float* gvec = (const float*)d_in[2];
    const float* Wj   = (const float*)d_in[3];
    const float* bj   = (const float*)d_in[4];
    const float* Wm   = (const float*)d_in[5];
    const float* bm   = (const float*)d_in[6];
    const float* Wg   = (const float*)d_in[7];
    const float* bg   = (const float*)d_in[8];
    const float* W1   = (const float*)d_in[9];
    const float* b1   = (const float*)d_in[10];
    const float* W2   = (const float*)d_in[11];
    const float* b2   = (const float*)d_in[12];
    float* out = (float*)d_out;

    const int N = in_sizes[0];
    const int M = in_sizes[1];

    // One warp per row: (N + M) rows, 8 warps per block.
    int rows = N + M;
    precompute_kernel<<<(rows + 7) / 8, 256>>>(
        job, mac, gvec, Wj, bj, Wm, bm, Wg, bg, W1, b1, N, M);

    dim3 grid(M / 64, N / 128);
    qmain_kernel<<<grid, 256>>>(W2, b2, out, N, M);
}

// round 3
// speedup vs baseline: 1.5222x; 1.0580x over previous
#include <cuda_runtime.h>
#include <cstdint>

// ---------------------------------------------------------------------------
// Q[n,m] = b2 + sum_h w2[h] * relu( hj[n,h] + hm'[m,h] )
//   hm' = hm + hg + b1 folded into machine rows.
// N = M = 2048, HIDDEN = 64. Feature rows precomputed, h-pair packed (f32x2).
// ---------------------------------------------------------------------------

#define NMAX 2048
#define HID  64
#define HP   32   // h pairs

// g_aT[h2][n] = pack(hj[n][2h2], hj[n][2h2+1])
// g_bT[h2][m] = pack(hm'[m][2h2], hm'[m][2h2+1])
__device__ unsigned long long g_aT[HP][NMAX];
__device__ unsigned long long g_bT[HP][NMAX];

__device__ __forceinline__ unsigned long long pack2(float lo, float hi) {
    return (unsigned long long)__float_as_uint(lo) |
           ((unsigned long long)__float_as_uint(hi) << 32);
}

// ---------------------------------------------------------------------------
// Precompute: one warp per row. lane = h-pair index (0..31).
// ---------------------------------------------------------------------------
__global__ void __launch_bounds__(256) precompute_kernel(
    const float* __restrict__ job, const float* __restrict__ mac,
    const float* __restrict__ gvec,
    const float* __restrict__ Wj, const float* __restrict__ bj,
    const float* __restrict__ Wm, const float* __restrict__ bm,
    const float* __restrict__ Wg, const float* __restrict__ bg,
    const float* __restrict__ W1, const float* __restrict__ b1,
    int n, int m)
{
    const int row  = blockIdx.x * 8 + (threadIdx.x >> 5);
    const int lane = threadIdx.x & 31;

    if (row < n) {
        const float x = job[row];
        float h0 = 0.0f, h1 = 0.0f;
        #pragma unroll
        for (int j = 0; j < 16; ++j) {
            float f = fmaxf(fmaf(x, Wj[j], bj[j]), 0.0f);
            float2 w = *(const float2*)&W1[j * HID + 2 * lane];
            h0 = fmaf(f, w.x, h0);
            h1 = fmaf(f, w.y, h1);
        }
        g_aT[lane][row] = pack2(h0, h1);
    } else if (row < n + m) {
        const int mm = row - n;
        const float x = mac[mm];
        float2 bb = *(const float2*)&b1[2 * lane];
        float h0 = bb.x, h1 = bb.y;
        #pragma unroll
        for (int k = 0; k < 8; ++k) {
            float gf = bg[k];
            #pragma unroll
            for (int i = 0; i < 8; ++i)
                gf = fmaf(gvec[i], Wg[i * 8 + k], gf);
            gf = fmaxf(gf, 0.0f);
            float2 w = *(const float2*)&W1[(32 + k) * HID + 2 * lane];
            h0 = fmaf(gf, w.x, h0);
            h1 = fmaf(gf, w.y, h1);
        }
        #pragma unroll
        for (int j = 0; j < 16; ++j) {
            float f = fmaxf(fmaf(x, Wm[j], bm[j]), 0.0f);
            float2 w = *(const float2*)&W1[(16 + j) * HID + 2 * lane];
            h0 = fmaf(f, w.x, h0);
            h1 = fmaf(f, w.y, h1);
        }
        g_bT[lane][mm] = pack2(h0, h1);
    }
}

// ---------------------------------------------------------------------------
// Core step: acc(f32x2) += relu2(a + b) * w.
// 2 fma-pipe ops (add2, fma2) + 2 alu ops (FMNMX). mov.b64 pack/unpack is
// eliminated by ptxas register-pair allocation.
// ---------------------------------------------------------------------------
__device__ __forceinline__ void step(unsigned long long& acc,
                                     unsigned long long a,
                                     unsigned long long b,
                                     unsigned long long w)
{
    asm("{\n\t"
        ".reg .b64 t;\n\t"
        ".reg .f32 lo, hi;\n\t"
        "add.rn.f32x2 t, %1, %2;\n\t"
        "mov.b64 {lo, hi}, t;\n\t"
        "max.f32 lo, lo, 0f00000000;\n\t"
        "max.f32 hi, hi, 0f00000000;\n\t"
        "mov.b64 t, {lo, hi};\n\t"
        "fma.rn.f32x2 %0, t, %3, %0;\n\t"
        "}"
        : "+l"(acc)
        : "l"(a), "l"(b), "l"(w));
}

// ---------------------------------------------------------------------------
// Main kernel: block tile 64(n) x 64(m), 256 threads, 4x4 per thread.
// 4 CTAs/SM (reg cap 64) -> 8 warps/SMSP for latency hiding; 1024 blocks
// for near-perfect per-SM work balance.
// ---------------------------------------------------------------------------
__global__ void __launch_bounds__(256, 4) qmain_kernel(
    const float* __restrict__ W2, const float* __restrict__ b2,
    float* __restrict__ out, int N, int M)
{
    __shared__ unsigned long long sA[HP][64];   // 16 KB
    __shared__ unsigned long long sB[HP][64];   // 16 KB
    __shared__ unsigned long long sW[HP];       // 256 B

    const int tid = threadIdx.x;
    const int nBase = blockIdx.y * 64;
    const int mBase = blockIdx.x * 64;

    if (tid < HP) {
        float2 w = *(const float2*)&W2[2 * tid];
        sW[tid] = pack2(w.x, w.y);
    }
    // Fill sA and sB: 2048 entries each / 256 threads = 8 each, coalesced.
    #pragma unroll
    for (int i = 0; i < 8; ++i) {
        int idx = tid + i * 256;
        int h2 = idx >> 6, l = idx & 63;
        sA[h2][l] = g_aT[h2][nBase + l];
        sB[h2][l] = g_bT[h2][mBase + l];
    }
    __syncthreads();

    const int tx = tid & 15;        // m dimension
    const int ty = tid >> 4;        // n dimension
    const int n0 = ty * 4;
    const int m0 = tx * 4;

    unsigned long long acc[4][4];
    #pragma unroll
    for (int i = 0; i < 4; ++i)
        #pragma unroll
        for (int j = 0; j < 4; ++j)
            acc[i][j] = 0ull;

    #pragma unroll 4
    for (int h2 = 0; h2 < HP; ++h2) {
        unsigned long long w = sW[h2];
        ulonglong2 a0 = *(const ulonglong2*)&sA[h2][n0 + 0];
        ulonglong2 a1 = *(const ulonglong2*)&sA[h2][n0 + 2];
        ulonglong2 b0 = *(const ulonglong2*)&sB[h2][m0 + 0];
        ulonglong2 b1 = *(const ulonglong2*)&sB[h2][m0 + 2];
        unsigned long long A[4] = {a0.x, a0.y, a1.x, a1.y};
        unsigned long long B[4] = {b0.x, b0.y, b1.x, b1.y};
        #pragma unroll
        for (int i = 0; i < 4; ++i)
            #pragma unroll
            for (int j = 0; j < 4; ++j)
                step(acc[i][j], A[i], B[j], w);
    }

    // Epilogue: combine h-pair lanes, add b2, vectorized store.
    const float bconst = b2[0];
    #pragma unroll
    for (int i = 0; i < 4; ++i) {
        float r[4];
        #pragma unroll
        for (int j = 0; j < 4; ++j) {
            unsigned long long u = acc[i][j];
            r[j] = __uint_as_float((unsigned)u) +
                   __uint_as_float((unsigned)(u >> 32)) + bconst;
        }
        float4 v = make_float4(r[0], r[1], r[2], r[3]);
        *(float4*)&out[(size_t)(nBase + n0 + i) * M + (mBase + m0)] = v;
    }
}

// ---------------------------------------------------------------------------
// Launch
// ---------------------------------------------------------------------------
extern "C" void kernel_launch(void* const* d_in, const int* in_sizes, int n_in,
                              void* d_out, int out_size)
{
    const float* job  = (const float*)d_in[0];
    const float* mac  = (const float*)d_in[1];
    const float* gvec = (const float*)d_in[2];
    const float* Wj   = (const float*)d_in[3];
    const float* bj   = (const float*)d_in[4];
    const float* Wm   = (const float*)d_in[5];
    const float* bm   = (const float*)d_in[6];
    const float* Wg   = (const float*)d_in[7];
    const float* bg   = (const float*)d_in[8];
    const float* W1   = (const float*)d_in[9];
    const float* b1   = (const float*)d_in[10];
    const float* W2   = (const float*)d_in[11];
    const float* b2   = (const float*)d_in[12];
    float* out = (float*)d_out;

    const int N = in_sizes[0];
    const int M = in_sizes[1];

    int rows = N + M;
    precompute_kernel<<<(rows + 7) / 8, 256>>>(
        job, mac, gvec, Wj, bj, Wm, bm, Wg, bg, W1, b1, N, M);

    dim3 grid(M / 64, N / 64);
    qmain_kernel<<<grid, 256>>>(W2, b2, out, N, M);
}

// round 4
// speedup vs baseline: 1.6129x; 1.0596x over previous
#include <cuda_runtime.h>
#include <cstdint>

// ---------------------------------------------------------------------------
// Q[n,m] = b2 + sum_h w2[h] * relu( hj[n,h] + hm'[m,h] )
// relu(x) = (x + |x|)/2  =>
// Q[n,m] = P[n] + R[m] + sum_h (w2[h]/2) * |a[n,h] + b[m,h]|
//   P[n] = b2 + sum_h (w2[h]/2) a[n,h],  R[m] = sum_h (w2[h]/2) b[m,h]
// Inner loop: packed f32x2 add + fma with |.| folded as operand modifier.
// ---------------------------------------------------------------------------

#define NMAX 2048
#define HID  64
#define HP   32   // h pairs

__device__ unsigned long long g_aT[HP][NMAX];  // pack(a[n][2h2], a[n][2h2+1])
__device__ unsigned long long g_bT[HP][NMAX];  // pack(b[m][2h2], b[m][2h2+1])
__device__ float g_P[NMAX];                    // rank-1 job term (+b2)
__device__ float g_R[NMAX];                    // rank-1 machine term

__device__ __forceinline__ unsigned long long pack2(float lo, float hi) {
    return (unsigned long long)__float_as_uint(lo) |
           ((unsigned long long)__float_as_uint(hi) << 32);
}

// ---------------------------------------------------------------------------
// Precompute: one warp per row. lane = h-pair index (0..31).
// Also reduces the rank-1 dot product (0.5*w2 . h) via warp shuffles.
// ---------------------------------------------------------------------------
__global__ void __launch_bounds__(256) precompute_kernel(
    const float* __restrict__ job, const float* __restrict__ mac,
    const float* __restrict__ gvec,
    const float* __restrict__ Wj, const float* __restrict__ bj,
    const float* __restrict__ Wm, const float* __restrict__ bm,
    const float* __restrict__ Wg, const float* __restrict__ bg,
    const float* __restrict__ W1, const float* __restrict__ b1,
    const float* __restrict__ W2, const float* __restrict__ b2,
    int n, int m)
{
    const int row  = blockIdx.x * 8 + (threadIdx.x >> 5);
    const int lane = threadIdx.x & 31;
    if (row >= n + m) return;

    float2 w2p = *(const float2*)&W2[2 * lane];

    if (row < n) {
        const float x = job[row];
        float h0 = 0.0f, h1 = 0.0f;
        #pragma unroll
        for (int j = 0; j < 16; ++j) {
            float f = fmaxf(fmaf(x, Wj[j], bj[j]), 0.0f);
            float2 w = *(const float2*)&W1[j * HID + 2 * lane];
            h0 = fmaf(f, w.x, h0);
            h1 = fmaf(f, w.y, h1);
        }
        g_aT[lane][row] = pack2(h0, h1);
        // rank-1 term: 0.5 * (w.h) + b2
        float s = h0 * w2p.x + h1 * w2p.y;
        #pragma unroll
        for (int d = 16; d > 0; d >>= 1)
            s += __shfl_xor_sync(0xFFFFFFFFu, s, d);
        if (lane == 0) g_P[row] = 0.5f * s + b2[0];
    } else {
        const int mm = row - n;
        const float x = mac[mm];
        float2 bb = *(const float2*)&b1[2 * lane];
        float h0 = bb.x, h1 = bb.y;
        #pragma unroll
        for (int k = 0; k < 8; ++k) {
            float gf = bg[k];
            #pragma unroll
            for (int i = 0; i < 8; ++i)
                gf = fmaf(gvec[i], Wg[i * 8 + k], gf);
            gf = fmaxf(gf, 0.0f);
            float2 w = *(const float2*)&W1[(32 + k) * HID + 2 * lane];
            h0 = fmaf(gf, w.x, h0);
            h1 = fmaf(gf, w.y, h1);
        }
        #pragma unroll
        for (int j = 0; j < 16; ++j) {
            float f = fmaxf(fmaf(x, Wm[j], bm[j]), 0.0f);
            float2 w = *(const float2*)&W1[(16 + j) * HID + 2 * lane];
            h0 = fmaf(f, w.x, h0);
            h1 = fmaf(f, w.y, h1);
        }
        g_bT[lane][mm] = pack2(h0, h1);
        float s = h0 * w2p.x + h1 * w2p.y;
        #pragma unroll
        for (int d = 16; d > 0; d >>= 1)
            s += __shfl_xor_sync(0xFFFFFFFFu, s, d);
        if (lane == 0) g_R[mm] = 0.5f * s;
    }
}

// ---------------------------------------------------------------------------
// Core step: acc(f32x2) += |a + b| * w   (w pre-scaled by 0.5)
// add2 + fma2, with abs expected to fold into the FFMA2 operand modifier.
// ---------------------------------------------------------------------------
__device__ __forceinline__ void step(unsigned long long& acc,
                                     unsigned long long a,
                                     unsigned long long b,
                                     unsigned long long w)
{
    asm("{\n\t"
        ".reg .b64 t;\n\t"
        ".reg .f32 lo, hi;\n\t"
        "add.rn.f32x2 t, %1, %2;\n\t"
        "mov.b64 {lo, hi}, t;\n\t"
        "abs.f32 lo, lo;\n\t"
        "abs.f32 hi, hi;\n\t"
        "mov.b64 t, {lo, hi};\n\t"
        "fma.rn.f32x2 %0, t, %3, %0;\n\t"
        "}"
        : "+l"(acc)
        : "l"(a), "l"(b), "l"(w));
}

// ---------------------------------------------------------------------------
// Main kernel: block tile 64(n) x 64(m), 256 threads, 4x4 per thread,
// 4 CTAs/SM.
// ---------------------------------------------------------------------------
__global__ void __launch_bounds__(256, 4) qmain_kernel(
    const float* __restrict__ W2,
    float* __restrict__ out, int N, int M)
{
    __shared__ unsigned long long sA[HP][64];   // 16 KB
    __shared__ unsigned long long sB[HP][64];   // 16 KB
    __shared__ unsigned long long sW[HP];       // 256 B (0.5*w2 pairs)
    __shared__ float sP[64];
    __shared__ float sR[64];

    const int tid = threadIdx.x;
    const int nBase = blockIdx.y * 64;
    const int mBase = blockIdx.x * 64;

    if (tid < HP) {
        float2 w = *(const float2*)&W2[2 * tid];
        sW[tid] = pack2(0.5f * w.x, 0.5f * w.y);
    }
    if (tid >= 64 && tid < 128)  sP[tid - 64]  = g_P[nBase + (tid - 64)];
    if (tid >= 128 && tid < 192) sR[tid - 128] = g_R[mBase + (tid - 128)];

    #pragma unroll
    for (int i = 0; i < 8; ++i) {
        int idx = tid + i * 256;
        int h2 = idx >> 6, l = idx & 63;
        sA[h2][l] = g_aT[h2][nBase + l];
        sB[h2][l] = g_bT[h2][mBase + l];
    }
    __syncthreads();

    const int tx = tid & 15;        // m dimension
    const int ty = tid >> 4;        // n dimension
    const int n0 = ty * 4;
    const int m0 = tx * 4;

    unsigned long long acc[4][4];
    #pragma unroll
    for (int i = 0; i < 4; ++i)
        #pragma unroll
        for (int j = 0; j < 4; ++j)
            acc[i][j] = 0ull;

    #pragma unroll 4
    for (int h2 = 0; h2 < HP; ++h2) {
        unsigned long long w = sW[h2];
        ulonglong2 a0 = *(const ulonglong2*)&sA[h2][n0 + 0];
        ulonglong2 a1 = *(const ulonglong2*)&sA[h2][n0 + 2];
        ulonglong2 b0 = *(const ulonglong2*)&sB[h2][m0 + 0];
        ulonglong2 b1 = *(const ulonglong2*)&sB[h2][m0 + 2];
        unsigned long long A[4] = {a0.x, a0.y, a1.x, a1.y};
        unsigned long long B[4] = {b0.x, b0.y, b1.x, b1.y};
        #pragma unroll
        for (int i = 0; i < 4; ++i)
            #pragma unroll
            for (int j = 0; j < 4; ++j)
                step(acc[i][j], A[i], B[j], w);
    }

    // Epilogue: r = acc.lo + acc.hi + P[n] + R[m]
    #pragma unroll
    for (int i = 0; i < 4; ++i) {
        const float pn = sP[n0 + i];
        float r[4];
        #pragma unroll
        for (int j = 0; j < 4; ++j) {
            unsigned long long u = acc[i][j];
            r[j] = (__uint_as_float((unsigned)u) +
                    __uint_as_float((unsigned)(u >> 32))) + (pn + sR[m0 + j]);
        }
        float4 v = make_float4(r[0], r[1], r[2], r[3]);
        *(float4*)&out[(size_t)(nBase + n0 + i) * M + (mBase + m0)] = v;
    }
}

// ---------------------------------------------------------------------------
// Launch
// ---------------------------------------------------------------------------
extern "C" void kernel_launch(void* const* d_in, const int* in_sizes, int n_in,
                              void* d_out, int out_size)
{
    const float* job  = (const float*)d_in[0];
    const float* mac  = (const float*)d_in[1];
    const float* gvec = (const float*)d_in[2];
    const float* Wj   = (const float*)d_in[3];
    const float* bj   = (const float*)d_in[4];
    const float* Wm   = (const float*)d_in[5];
    const float* bm   = (const float*)d_in[6];
    const float* Wg   = (const float*)d_in[7];
    const float* bg   = (const float*)d_in[8];
    const float* W1   = (const float*)d_in[9];
    const float* b1   = (const float*)d_in[10];
    const float* W2   = (const float*)d_in[11];
    const float* b2   = (const float*)d_in[12];
    float* out = (float*)d_out;

    const int N = in_sizes[0];
    const int M = in_sizes[1];

    int rows = N + M;
    precompute_kernel<<<(rows + 7) / 8, 256>>>(
        job, mac, gvec, Wj, bj, Wm, bm, Wg, bg, W1, b1, W2, b2, N, M);

    dim3 grid(M / 64, N / 64);
    qmain_kernel<<<grid, 256>>>(W2, out, N, M);
}

// round 5
// speedup vs baseline: 1.8430x; 1.1427x over previous
#include <cuda_runtime.h>
#include <cstdint>

// ---------------------------------------------------------------------------
// Q[n,m] = P[n] + R[m] + sum_h (w2[h]/2) * |a[n,h] + b[m,h]|
//   (relu(x) = (x+|x|)/2 ; rank-1 halves folded into per-row P/R)
// Inner loop: packed f32x2 add + fma, |.| folded as FFMA2 operand modifier.
// Block: 128 threads, 64x64 tile, 8n x 4m per thread (fma-bound balance).
// ---------------------------------------------------------------------------

#define NMAX 2048
#define HID  64
#define HP   32   // h pairs

__device__ unsigned long long g_aT[HP][NMAX];  // pack(a[n][2h2], a[n][2h2+1])
__device__ unsigned long long g_bT[HP][NMAX];  // pack(b[m][2h2], b[m][2h2+1])
__device__ float g_P[NMAX];
__device__ float g_R[NMAX];

__device__ __forceinline__ unsigned long long pack2(float lo, float hi) {
    return (unsigned long long)__float_as_uint(lo) |
           ((unsigned long long)__float_as_uint(hi) << 32);
}

// ---------------------------------------------------------------------------
// Precompute: one warp per row; lane = h-pair. Warp-shuffle rank-1 reduce.
// ---------------------------------------------------------------------------
__global__ void __launch_bounds__(256) precompute_kernel(
    const float* __restrict__ job, const float* __restrict__ mac,
    const float* __restrict__ gvec,
    const float* __restrict__ Wj, const float* __restrict__ bj,
    const float* __restrict__ Wm, const float* __restrict__ bm,
    const float* __restrict__ Wg, const float* __restrict__ bg,
    const float* __restrict__ W1, const float* __restrict__ b1,
    const float* __restrict__ W2, const float* __restrict__ b2,
    int n, int m)
{
    const int row  = blockIdx.x * 8 + (threadIdx.x >> 5);
    const int lane = threadIdx.x & 31;
    if (row >= n + m) return;

    float2 w2p = *(const float2*)&W2[2 * lane];

    if (row < n) {
        const float x = job[row];
        float h0 = 0.0f, h1 = 0.0f;
        #pragma unroll
        for (int j = 0; j < 16; ++j) {
            float f = fmaxf(fmaf(x, Wj[j], bj[j]), 0.0f);
            float2 w = *(const float2*)&W1[j * HID + 2 * lane];
            h0 = fmaf(f, w.x, h0);
            h1 = fmaf(f, w.y, h1);
        }
        g_aT[lane][row] = pack2(h0, h1);
        float s = h0 * w2p.x + h1 * w2p.y;
        #pragma unroll
        for (int d = 16; d > 0; d >>= 1)
            s += __shfl_xor_sync(0xFFFFFFFFu, s, d);
        if (lane == 0) g_P[row] = 0.5f * s + b2[0];
    } else {
        const int mm = row - n;
        const float x = mac[mm];
        float2 bb = *(const float2*)&b1[2 * lane];
        float h0 = bb.x, h1 = bb.y;
        #pragma unroll
        for (int k = 0; k < 8; ++k) {
            float gf = bg[k];
            #pragma unroll
            for (int i = 0; i < 8; ++i)
                gf = fmaf(gvec[i], Wg[i * 8 + k], gf);
            gf = fmaxf(gf, 0.0f);
            float2 w = *(const float2*)&W1[(32 + k) * HID + 2 * lane];
            h0 = fmaf(gf, w.x, h0);
            h1 = fmaf(gf, w.y, h1);
        }
        #pragma unroll
        for (int j = 0; j < 16; ++j) {
            float f = fmaxf(fmaf(x, Wm[j], bm[j]), 0.0f);
            float2 w = *(const float2*)&W1[(16 + j) * HID + 2 * lane];
            h0 = fmaf(f, w.x, h0);
            h1 = fmaf(f, w.y, h1);
        }
        g_bT[lane][mm] = pack2(h0, h1);
        float s = h0 * w2p.x + h1 * w2p.y;
        #pragma unroll
        for (int d = 16; d > 0; d >>= 1)
            s += __shfl_xor_sync(0xFFFFFFFFu, s, d);
        if (lane == 0) g_R[mm] = 0.5f * s;
    }
}

// ---------------------------------------------------------------------------
// Core step: acc(f32x2) += |a + b| * w   (w pre-scaled by 0.5)
// ---------------------------------------------------------------------------
__device__ __forceinline__ void step(unsigned long long& acc,
                                     unsigned long long a,
                                     unsigned long long b,
                                     unsigned long long w)
{
    asm("{\n\t"
        ".reg .b64 t;\n\t"
        ".reg .f32 lo, hi;\n\t"
        "add.rn.f32x2 t, %1, %2;\n\t"
        "mov.b64 {lo, hi}, t;\n\t"
        "abs.f32 lo, lo;\n\t"
        "abs.f32 hi, hi;\n\t"
        "mov.b64 t, {lo, hi};\n\t"
        "fma.rn.f32x2 %0, t, %3, %0;\n\t"
        "}"
        : "+l"(acc)
        : "l"(a), "l"(b), "l"(w));
}

// ---------------------------------------------------------------------------
// Main kernel: 128 threads, block tile 64(n) x 64(m), 8n x 4m per thread.
// 4 CTAs/SM. Thread map: ty = tid>>4 (8 rows of 8n), tx = tid&15 (16 cols of 4m).
// ---------------------------------------------------------------------------
__global__ void __launch_bounds__(128, 4) qmain_kernel(
    const float* __restrict__ W2,
    float* __restrict__ out, int N, int M)
{
    __shared__ unsigned long long sA[HP][64];   // 16 KB
    __shared__ unsigned long long sB[HP][64];   // 16 KB
    __shared__ unsigned long long sW[HP];       // 256 B (0.5*w2 pairs)
    __shared__ float sP[64];
    __shared__ float sR[64];

    const int tid = threadIdx.x;
    const int nBase = blockIdx.y * 64;
    const int mBase = blockIdx.x * 64;

    if (tid < HP) {
        float2 w = *(const float2*)&W2[2 * tid];
        sW[tid] = pack2(0.5f * w.x, 0.5f * w.y);
    }
    if (tid < 64) sP[tid] = g_P[nBase + tid];
    else          sR[tid - 64] = g_R[mBase + (tid - 64)];

    // Fill sA, sB: 2048 entries each / 128 threads = 16 each, coalesced.
    #pragma unroll
    for (int i = 0; i < 16; ++i) {
        int idx = tid + i * 128;
        int h2 = idx >> 6, l = idx & 63;
        sA[h2][l] = g_aT[h2][nBase + l];
        sB[h2][l] = g_bT[h2][mBase + l];
    }
    __syncthreads();

    const int tx = tid & 15;        // m dimension: 16 x 4
    const int ty = tid >> 4;        // n dimension: 8 x 8
    const int n0 = ty * 8;
    const int m0 = tx * 4;

    unsigned long long acc[8][4];
    #pragma unroll
    for (int i = 0; i < 8; ++i)
        #pragma unroll
        for (int j = 0; j < 4; ++j)
            acc[i][j] = 0ull;

    #pragma unroll 2
    for (int h2 = 0; h2 < HP; ++h2) {
        unsigned long long w = sW[h2];
        ulonglong2 a0 = *(const ulonglong2*)&sA[h2][n0 + 0];
        ulonglong2 a1 = *(const ulonglong2*)&sA[h2][n0 + 2];
        ulonglong2 a2 = *(const ulonglong2*)&sA[h2][n0 + 4];
        ulonglong2 a3 = *(const ulonglong2*)&sA[h2][n0 + 6];
        ulonglong2 b0 = *(const ulonglong2*)&sB[h2][m0 + 0];
        ulonglong2 b1 = *(const ulonglong2*)&sB[h2][m0 + 2];
        unsigned long long A[8] = {a0.x, a0.y, a1.x, a1.y, a2.x, a2.y, a3.x, a3.y};
        unsigned long long B[4] = {b0.x, b0.y, b1.x, b1.y};
        #pragma unroll
        for (int i = 0; i < 8; ++i)
            #pragma unroll
            for (int j = 0; j < 4; ++j)
                step(acc[i][j], A[i], B[j], w);
    }

    // Epilogue: r = acc.lo + acc.hi + P[n] + R[m]
    #pragma unroll
    for (int i = 0; i < 8; ++i) {
        const float pn = sP[n0 + i];
        float r[4];
        #pragma unroll
        for (int j = 0; j < 4; ++j) {
            unsigned long long u = acc[i][j];
            r[j] = (__uint_as_float((unsigned)u) +
                    __uint_as_float((unsigned)(u >> 32))) + (pn + sR[m0 + j]);
        }
        float4 v = make_float4(r[0], r[1], r[2], r[3]);
        *(float4*)&out[(size_t)(nBase + n0 + i) * M + (mBase + m0)] = v;
    }
}

// ---------------------------------------------------------------------------
// Launch
// ---------------------------------------------------------------------------
extern "C" void kernel_launch(void* const* d_in, const int* in_sizes, int n_in,
                              void* d_out, int out_size)
{
    const float* job  = (const float*)d_in[0];
    const float* mac  = (const float*)d_in[1];
    const float* gvec = (const float*)d_in[2];
    const float* Wj   = (const float*)d_in[3];
    const float* bj   = (const float*)d_in[4];
    const float* Wm   = (const float*)d_in[5];
    const float* bm   = (const float*)d_in[6];
    const float* Wg   = (const float*)d_in[7];
    const float* bg   = (const float*)d_in[8];
    const float* W1   = (const float*)d_in[9];
    const float* b1   = (const float*)d_in[10];
    const float* W2   = (const float*)d_in[11];
    const float* b2   = (const float*)d_in[12];
    float* out = (float*)d_out;

    const int N = in_sizes[0];
    const int M = in_sizes[1];

    int rows = N + M;
    precompute_kernel<<<(rows + 7) / 8, 256>>>(
        job, mac, gvec, Wj, bj, Wm, bm, Wg, bg, W1, b1, W2, b2, N, M);

    dim3 grid(M / 64, N / 64);
    qmain_kernel<<<grid, 128>>>(W2, out, N, M);
}